// round 4
// baseline (speedup 1.0000x reference)
#include <cuda_runtime.h>
#include <cuda_fp16.h>
#include <stdint.h>

// MX fp8 (e4m3) fake quantization, block=32, shared e8m0 exponent.
//
// Warp tile: 1024 consecutive floats (256 float4, 32 quant blocks).
// Each lane front-batches 8 coalesced float4 loads (j*32 + lane); load j of
// 8-lane group g covers quant block 4j+g. Block amax matters only via its
// fp32 exponent field (exp-field max == exp field of amax for nonneg
// floats), so per-load exponent bytes are packed 4-per-u32 and reduced with
// 3x shfl.bfly + __vmaxu4 (two packed words cover all 8 loads).
//
// Element quantization uses the HW e4m3 converter:
//   cvt.rn.satfinite.e4m3x2.f32 == round-half-even onto the e4m3 grid
//   (subnormal step 2^-9, saturate to +-448)
// bit-identical to the reference's priv_exp/pscale/round/clip chain; decode
// is exact via cvt.rn.f16x2.e4m3x2 + f16->f32.

static __device__ __forceinline__ float2 qdq_pair(float x, float y,
                                                  float inv, float scale) {
    float xs = x * inv;                       // exact (power-of-2 scale)
    float ys = y * inv;
    unsigned short p8;
    asm("cvt.rn.satfinite.e4m3x2.f32 %0, %1, %2;"
        : "=h"(p8) : "f"(ys), "f"(xs));       // x -> lo byte
    unsigned h2;
    asm("cvt.rn.f16x2.e4m3x2 %0, %1;" : "=r"(h2) : "h"(p8));
    __half2 hh = *reinterpret_cast<__half2*>(&h2);   // lo=x, hi=y (exact)
    float2 f = __half22float2(hh);
    f.x *= scale;
    f.y *= scale;
    return f;
}

static __device__ __forceinline__ unsigned expbyte4(const float4& v0,
                                                    const float4& v1,
                                                    const float4& v2,
                                                    const float4& v3) {
    float a0 = fmaxf(fmaxf(fabsf(v0.x), fabsf(v0.y)), fmaxf(fabsf(v0.z), fabsf(v0.w)));
    float a1 = fmaxf(fmaxf(fabsf(v1.x), fabsf(v1.y)), fmaxf(fabsf(v1.z), fabsf(v1.w)));
    float a2 = fmaxf(fmaxf(fabsf(v2.x), fabsf(v2.y)), fmaxf(fabsf(v2.z), fabsf(v2.w)));
    float a3 = fmaxf(fmaxf(fabsf(v3.x), fabsf(v3.y)), fmaxf(fabsf(v3.z), fabsf(v3.w)));
    return (__float_as_uint(a0) >> 23)
         | ((__float_as_uint(a1) >> 23) << 8)
         | ((__float_as_uint(a2) >> 23) << 16)
         | ((__float_as_uint(a3) >> 23) << 24);
}

__global__ void __launch_bounds__(256) mx_fp8_fq_kernel(
    const float4* __restrict__ in, float4* __restrict__ out) {
    int warp = (blockIdx.x * blockDim.x + threadIdx.x) >> 5;
    int lane = threadIdx.x & 31;
    int idx0 = warp * 256 + lane;

    // Front-batched loads: 8 LDG.128 in flight per thread.
    float4 v[8];
#pragma unroll
    for (int j = 0; j < 8; j++) v[j] = __ldcs(&in[idx0 + 32 * j]);

    unsigned p0 = expbyte4(v[0], v[1], v[2], v[3]);
    unsigned p1 = expbyte4(v[4], v[5], v[6], v[7]);

    // Segmented (8-lane) reduction of all 8 block exponents at once.
    p0 = __vmaxu4(p0, __shfl_xor_sync(0xffffffffu, p0, 1));
    p1 = __vmaxu4(p1, __shfl_xor_sync(0xffffffffu, p1, 1));
    p0 = __vmaxu4(p0, __shfl_xor_sync(0xffffffffu, p0, 2));
    p1 = __vmaxu4(p1, __shfl_xor_sync(0xffffffffu, p1, 2));
    p0 = __vmaxu4(p0, __shfl_xor_sync(0xffffffffu, p0, 4));
    p1 = __vmaxu4(p1, __shfl_xor_sync(0xffffffffu, p1, 4));

#pragma unroll
    for (int j = 0; j < 8; j++) {
        unsigned packed = (j < 4) ? p0 : p1;
        int e = (packed >> (8 * (j & 3))) & 0xff;
        int sexp = max(e - 135, -127);   // floor(log2(amax)) - 8, clipped low
        // scale = 2^sexp (sexp==-127 -> subnormal 0x00400000); inv = 2^-sexp.
        float scale = __int_as_float(max((sexp + 127) << 23, 0x00400000));
        float inv   = __int_as_float((127 - sexp) << 23);
        float2 lo = qdq_pair(v[j].x, v[j].y, inv, scale);
        float2 hi = qdq_pair(v[j].z, v[j].w, inv, scale);
        __stcs(&out[idx0 + 32 * j], make_float4(lo.x, lo.y, hi.x, hi.y));
    }
}

extern "C" void kernel_launch(void* const* d_in, const int* in_sizes, int n_in,
                              void* d_out, int out_size) {
    const float4* in = (const float4*)d_in[0];
    float4* out = (float4*)d_out;
    int n = in_sizes[0];              // 8192*8192
    int n4 = n / 4;                   // 16,777,216 float4
    int warps = n4 / 256;             // 256 float4 per warp -> 65536 warps
    int blocks = warps / 8;           // 8 warps per block -> 8192 blocks
    mx_fp8_fq_kernel<<<blocks, 256>>>(in, out);
}